// round 6
// baseline (speedup 1.0000x reference)
#include <cuda_runtime.h>
#include <cstdint>

// ===========================================================================
// OctreeGnResBlock2 via mma.sync tf32 + deep cp.async pipelines.
//   prep : W -> K-major tf32; x -> tf32; neigh -> [k][node]
//   kA   : h  = relu(GN_a(sum_k gather(x) @ Wa[k]))   (+ shortcut tap:
//          sc = GN_s(x @ W1) -> g_sc), depth-3 tap pipeline
//   kB   : out= relu(GN_b(sum_k gather(h) @ Wb[k]) + g_sc)
//          54 K=32 half-taps, depth-4 pipeline (wait_group 2)
// CTA = 128 nodes / 256 thr; 8 warps tile 128x64 as 4(m32) x 2(n32).
// Stages are 24KB (A 16KB + W 8KB), XOR-swizzled 16B blocks, conflict-free.
// ===========================================================================

__device__ float g_h  [800000ULL * 64];  // tf32-rounded activations
__device__ float g_sc [800000ULL * 64];  // GN_s(x @ W1), fp32
__device__ float g_xt [800000ULL * 32];  // tf32-rounded input
__device__ int   g_neiT[27 * 800000];    // neigh transposed [k][node]
__device__ float g_Wat[27 * 64 * 32];    // [k][cout][cin] tf32
__device__ float g_Wbt[27 * 64 * 64];
__device__ float g_W1t[64 * 32];

__device__ __forceinline__ float totf32(float f) {
    uint32_t u;
    asm("cvt.rna.tf32.f32 %0, %1;" : "=r"(u) : "f"(f));
    return __uint_as_float(u);
}
__device__ __forceinline__ uint32_t s2u(const void* p) {
    uint32_t a;
    asm("{ .reg .u64 t; cvta.to.shared.u64 t, %1; cvt.u32.u64 %0, t; }"
        : "=r"(a) : "l"(p));
    return a;
}
__device__ __forceinline__ void cpa16(uint32_t d, const void* s) {
    asm volatile("cp.async.cg.shared.global [%0], [%1], 16;" :: "r"(d), "l"(s));
}
#define CPA_COMMIT() asm volatile("cp.async.commit_group;" ::: "memory")
#define CPA_WAIT(N)  asm volatile("cp.async.wait_group %0;" :: "n"(N) : "memory")

#define MMA(c, a, b0, b1)                                                    \
    asm volatile(                                                            \
        "mma.sync.aligned.m16n8k8.row.col.f32.tf32.tf32.f32 "                \
        "{%0,%1,%2,%3},{%4,%5,%6,%7},{%8,%9},{%0,%1,%2,%3};"                 \
        : "+f"((c)[0]), "+f"((c)[1]), "+f"((c)[2]), "+f"((c)[3])             \
        : "r"((a)[0]), "r"((a)[1]), "r"((a)[2]), "r"((a)[3]),                \
          "r"(b0), "r"(b1))

// one K=32 stage: A[128x32] @ B[64x32]^T into c[2][4][4] (rows = 8 blk swz)
__device__ __forceinline__ void tap_mma32(const float* __restrict__ sA,
                                          const float* __restrict__ sW,
                                          float c[2][4][4], int lid, int wid) {
    const int g = lid >> 2, t = lid & 3;
    const float* pa = sA + ((wid & 3) * 32 + g) * 32 + t;
    const float* pb = sW + ((wid >> 2) * 32 + g) * 32 + t;
#pragma unroll
    for (int s = 0; s < 4; ++s) {
        const int o0 = (((2 * s) & 7) ^ g) * 4;
        const int o1 = (((2 * s + 1) & 7) ^ g) * 4;
        uint32_t a[2][4];
#pragma unroll
        for (int m = 0; m < 2; ++m) {
            const float* p = pa + m * 16 * 32;
            a[m][0] = __float_as_uint(p[o0]);
            a[m][1] = __float_as_uint(p[8 * 32 + o0]);
            a[m][2] = __float_as_uint(p[o1]);
            a[m][3] = __float_as_uint(p[8 * 32 + o1]);
        }
#pragma unroll
        for (int nn = 0; nn < 4; ++nn) {
            const float* q = pb + nn * 8 * 32;
            const uint32_t b0 = __float_as_uint(q[o0]);
            const uint32_t b1 = __float_as_uint(q[o1]);
            MMA(c[0][nn], a[0], b0, b1);
            MMA(c[1][nn], a[1], b0, b1);
        }
    }
}

// ---------------- prep ----------------
__global__ void k_prepW(const float* __restrict__ Wa,
                        const float* __restrict__ Wb,
                        const float* __restrict__ W1) {
    const int t = blockIdx.x * 256 + threadIdx.x;
    if (t < 27 * 64 * 32) {
        const int k = t / 2048, o = (t % 2048) / 32, i = t % 32;
        g_Wat[t] = totf32(Wa[k * 2048 + i * 64 + o]);
    }
    if (t < 27 * 64 * 64) {
        const int k = t / 4096, o = (t % 4096) / 64, i = t % 64;
        g_Wbt[t] = totf32(Wb[k * 4096 + i * 64 + o]);
    }
    if (t < 2048) {
        const int o = t / 32, i = t % 32;
        g_W1t[t] = totf32(W1[i * 64 + o]);
    }
}
__global__ void k_prepX(const float* __restrict__ x, long long n32) {
    for (long long i = blockIdx.x * 256LL + threadIdx.x; i < n32;
         i += (long long)gridDim.x * 256)
        g_xt[i] = totf32(x[i]);
}
__global__ void k_prepN(const int* __restrict__ neigh, int n) {
    const int i = blockIdx.x * 256 + threadIdx.x;
    if (i < n) {
        int v[27];
#pragma unroll
        for (int k = 0; k < 27; ++k) v[k] = neigh[(long long)i * 27 + k];
#pragma unroll
        for (int k = 0; k < 27; ++k) g_neiT[(size_t)k * n + i] = v[k];
    }
}

// ---------------- kernel A: 28 K=32 taps (27 conv + shortcut), depth 3 ------
static constexpr int STG = 24576;             // A 16KB + W 8KB
static constexpr int A_SM = 3 * STG;          // 73728

__global__ void __launch_bounds__(256, 2) kA(
    const float* __restrict__ gw, const float* __restrict__ gb,
    const float* __restrict__ gsw, const float* __restrict__ gsb, int n)
{
    extern __shared__ char smem[];
    const uint32_t sbase = s2u(smem);
    const int tid = threadIdx.x, wid = tid >> 5, lid = tid & 31;
    const int tile = blockIdx.x;
    const int rows = min(128, n - tile * 128);

    float c[2][4][4], csc[2][4][4];
#pragma unroll
    for (int m = 0; m < 2; ++m)
#pragma unroll
        for (int nn = 0; nn < 4; ++nn)
#pragma unroll
            for (int j = 0; j < 4; ++j) { c[m][nn][j] = 0.f; csc[m][nn][j] = 0.f; }

    auto stage = [&](int j) {
        const uint32_t aB = sbase + (uint32_t)(j % 3) * STG;
        const uint32_t wB = aB + 16384u;
        if (j < 27) {
            const int* nT = g_neiT + (size_t)j * n;
#pragma unroll
            for (int q = 0; q < 4; ++q) {
                const int lin = tid + q * 256, row = lin >> 3, seg = lin & 7;
                const int nd = tile * 128 + ((row < rows) ? row : 0);
                const long long idx = nT[nd];
                cpa16(aB + (row * 8 + (seg ^ (row & 7))) * 16,
                      g_xt + idx * 32 + seg * 4);
            }
#pragma unroll
            for (int q = 0; q < 2; ++q) {
                const int lin = tid + q * 256, row = lin >> 3, seg = lin & 7;
                cpa16(wB + (row * 8 + (seg ^ (row & 7))) * 16,
                      g_Wat + j * 2048 + row * 32 + seg * 4);
            }
        } else {                                // shortcut: A = x, W = W1t
#pragma unroll
            for (int q = 0; q < 4; ++q) {
                const int lin = tid + q * 256, row = lin >> 3, seg = lin & 7;
                const long long nd = tile * 128 + ((row < rows) ? row : 0);
                cpa16(aB + (row * 8 + (seg ^ (row & 7))) * 16,
                      g_xt + nd * 32 + seg * 4);
            }
#pragma unroll
            for (int q = 0; q < 2; ++q) {
                const int lin = tid + q * 256, row = lin >> 3, seg = lin & 7;
                cpa16(wB + (row * 8 + (seg ^ (row & 7))) * 16,
                      g_W1t + row * 32 + seg * 4);
            }
        }
        CPA_COMMIT();
    };

    stage(0); stage(1);
    for (int j = 0; j < 28; ++j) {
        CPA_WAIT(1);
        __syncthreads();
        if (j + 2 < 28) stage(j + 2); else CPA_COMMIT();   // keep group count
        const float* aF = (const float*)(smem + (j % 3) * STG);
        const float* wF = aF + 4096;
        tap_mma32(aF, wF, (j < 27) ? c : csc, lid, wid);
    }

    const int g = lid >> 2, t = lid & 3;
    const int mbase = (wid & 3) * 32, nbase = (wid >> 2) * 32;
#pragma unroll
    for (int m = 0; m < 2; ++m)
#pragma unroll
        for (int h = 0; h < 2; ++h) {
            const int row = mbase + m * 16 + g + h * 8;
#pragma unroll
            for (int nn = 0; nn < 4; ++nn) {
                // GN_a + ReLU -> h (tf32-rounded)
                const float v0 = c[m][nn][h * 2], v1 = c[m][nn][h * 2 + 1];
                float s = v0 + v1;
                s += __shfl_xor_sync(0xffffffffu, s, 1);
                const float mu = s * 0.25f;
                const float d0 = v0 - mu, d1 = v1 - mu;
                float q = d0 * d0 + d1 * d1;
                q += __shfl_xor_sync(0xffffffffu, q, 1);
                const float rs = rsqrtf(q * 0.25f + 1e-5f);
                // GN_s -> sc (fp32)
                const float w0 = csc[m][nn][h * 2], w1 = csc[m][nn][h * 2 + 1];
                float s2 = w0 + w1;
                s2 += __shfl_xor_sync(0xffffffffu, s2, 1);
                const float mus = s2 * 0.25f;
                const float e0 = w0 - mus, e1 = w1 - mus;
                float q2 = e0 * e0 + e1 * e1;
                q2 += __shfl_xor_sync(0xffffffffu, q2, 1);
                const float rss = rsqrtf(q2 * 0.25f + 1e-5f);

                const int col = nbase + nn * 8 + t * 2;
                if (row < rows) {
                    const long long base = ((long long)tile * 128 + row) * 64 + col;
                    float2 oh;
                    oh.x = totf32(fmaxf(fmaf(d0 * rs, __ldg(gw + col),
                                             __ldg(gb + col)), 0.f));
                    oh.y = totf32(fmaxf(fmaf(d1 * rs, __ldg(gw + col + 1),
                                             __ldg(gb + col + 1)), 0.f));
                    *(float2*)(g_h + base) = oh;
                    float2 os;
                    os.x = fmaf(e0 * rss, __ldg(gsw + col), __ldg(gsb + col));
                    os.y = fmaf(e1 * rss, __ldg(gsw + col + 1), __ldg(gsb + col + 1));
                    *(float2*)(g_sc + base) = os;
                }
            }
        }
}

// ---------------- kernel B: 54 K=32 half-taps, depth 4 ----------------------
static constexpr int B_SM = 4 * STG;          // 98304

__global__ void __launch_bounds__(256, 2) kB(
    const float* __restrict__ gbw, const float* __restrict__ gbb,
    float* __restrict__ out, int n)
{
    extern __shared__ char smem[];
    const uint32_t sbase = s2u(smem);
    const int tid = threadIdx.x, wid = tid >> 5, lid = tid & 31;
    const int tile = blockIdx.x;
    const int rows = min(128, n - tile * 128);

    float c[2][4][4];
#pragma unroll
    for (int m = 0; m < 2; ++m)
#pragma unroll
        for (int nn = 0; nn < 4; ++nn)
#pragma unroll
            for (int j = 0; j < 4; ++j) c[m][nn][j] = 0.f;

    auto stage = [&](int s) {
        const int k = s >> 1, hf = s & 1;
        const uint32_t aB = sbase + (uint32_t)(s & 3) * STG;
        const uint32_t wB = aB + 16384u;
        const int* nT = g_neiT + (size_t)k * n;
#pragma unroll
        for (int q = 0; q < 4; ++q) {
            const int lin = tid + q * 256, row = lin >> 3, seg = lin & 7;
            const int nd = tile * 128 + ((row < rows) ? row : 0);
            const long long idx = nT[nd];
            cpa16(aB + (row * 8 + (seg ^ (row & 7))) * 16,
                  g_h + idx * 64 + hf * 32 + seg * 4);
        }
#pragma unroll
        for (int q = 0; q < 2; ++q) {
            const int lin = tid + q * 256, row = lin >> 3, seg = lin & 7;
            cpa16(wB + (row * 8 + (seg ^ (row & 7))) * 16,
                  g_Wbt + k * 4096 + row * 64 + hf * 32 + seg * 4);
        }
        CPA_COMMIT();
    };

    stage(0); stage(1); stage(2);
    for (int s = 0; s < 54; ++s) {
        CPA_WAIT(2);
        __syncthreads();
        if (s + 3 < 54) stage(s + 3); else CPA_COMMIT();
        const float* aF = (const float*)(smem + (s & 3) * STG);
        tap_mma32(aF, aF + 4096, c, lid, wid);
    }

    const int g = lid >> 2, t = lid & 3;
    const int mbase = (wid & 3) * 32, nbase = (wid >> 2) * 32;
#pragma unroll
    for (int m = 0; m < 2; ++m)
#pragma unroll
        for (int h = 0; h < 2; ++h) {
            const int row = mbase + m * 16 + g + h * 8;
#pragma unroll
            for (int nn = 0; nn < 4; ++nn) {
                const float v0 = c[m][nn][h * 2], v1 = c[m][nn][h * 2 + 1];
                float s = v0 + v1;
                s += __shfl_xor_sync(0xffffffffu, s, 1);
                const float mub = s * 0.25f;
                const float d0 = v0 - mub, d1 = v1 - mub;
                float q = d0 * d0 + d1 * d1;
                q += __shfl_xor_sync(0xffffffffu, q, 1);
                const float rb = rsqrtf(q * 0.25f + 1e-5f);

                const int col = nbase + nn * 8 + t * 2;
                if (row < rows) {
                    const long long base = ((long long)tile * 128 + row) * 64 + col;
                    const float2 sc = *(const float2*)(g_sc + base);
                    float2 o;
                    o.x = fmaxf(fmaf(d0 * rb, __ldg(gbw + col),
                                     __ldg(gbb + col)) + sc.x, 0.f);
                    o.y = fmaxf(fmaf(d1 * rb, __ldg(gbw + col + 1),
                                     __ldg(gbb + col + 1)) + sc.y, 0.f);
                    *(float2*)(out + base) = o;
                }
            }
        }
}

// ---------------------------------------------------------------------------
extern "C" void kernel_launch(void* const* d_in, const int* in_sizes, int n_in,
                              void* d_out, int out_size) {
    const float* data  = (const float*)d_in[0];
    const int*   neigh = (const int*)d_in[1];
    const float* Wa    = (const float*)d_in[2];
    const float* ga_w  = (const float*)d_in[3];
    const float* ga_b  = (const float*)d_in[4];
    const float* Wb    = (const float*)d_in[5];
    const float* gb_w  = (const float*)d_in[6];
    const float* gb_b  = (const float*)d_in[7];
    const float* W1    = (const float*)d_in[8];
    const float* gs_w  = (const float*)d_in[9];
    const float* gs_b  = (const float*)d_in[10];
    float* out = (float*)d_out;

    const int n = in_sizes[0] / 32;
    const int tiles = (n + 127) / 128;

    cudaFuncSetAttribute(kA, cudaFuncAttributeMaxDynamicSharedMemorySize, A_SM);
    cudaFuncSetAttribute(kB, cudaFuncAttributeMaxDynamicSharedMemorySize, B_SM);

    k_prepW<<<(27 * 64 * 64 + 255) / 256, 256>>>(Wa, Wb, W1);
    k_prepX<<<2048, 256>>>(data, (long long)n * 32);
    k_prepN<<<(n + 255) / 256, 256>>>(neigh, n);
    kA<<<tiles, 256, A_SM>>>(ga_w, ga_b, gs_w, gs_b, n);
    kB<<<tiles, 256, B_SM>>>(gb_w, gb_b, out, n);
}